// round 13
// baseline (speedup 1.0000x reference)
#include <cuda_runtime.h>
#include <cuda_bf16.h>
#include <math.h>
#include <stdint.h>

// ---------------------------------------------------------------------------
// Problem constants
//   x: (8, 256, 32, 32)  -> [b][c][s], s = 1024
//   w_qkv: (1536, 256), w_out: (256, 512), b_out: (256,)
//   HEADS=8, DIM_HEAD=64, SCALE=10, ROT_DIM=32 (16 freqs)
//   L2 norm over the SEQUENCE axis (per (b,h,d) row), per reference.
// ---------------------------------------------------------------------------
#define B_   8
#define C_   256
#define S_   1024
#define H_   8
#define D_   64
#define HID_ 512
#define O1_  1536

__device__ float g_qkv[B_ * O1_ * S_];     // [b][o][s]
__device__ float g_att[B_ * HID_ * S_];    // [b][h*64+d][s]
__device__ float g_sin[S_ * 16];
__device__ float g_cos[S_ * 16];

// ---------------------------------------------------------------------------
// MMA helpers
// ---------------------------------------------------------------------------
__device__ __forceinline__ void mma_tf32(float c[4],
    uint32_t a0, uint32_t a1, uint32_t a2, uint32_t a3,
    uint32_t b0, uint32_t b1)
{
    asm volatile(
        "mma.sync.aligned.m16n8k8.row.col.f32.tf32.tf32.f32 "
        "{%0,%1,%2,%3}, {%4,%5,%6,%7}, {%8,%9}, {%0,%1,%2,%3};"
        : "+f"(c[0]), "+f"(c[1]), "+f"(c[2]), "+f"(c[3])
        : "r"(a0), "r"(a1), "r"(a2), "r"(a3), "r"(b0), "r"(b1));
}

__device__ __forceinline__ void mma_bf16(float c[4],
    uint32_t a0, uint32_t a1, uint32_t a2, uint32_t a3,
    uint32_t b0, uint32_t b1)
{
    asm volatile(
        "mma.sync.aligned.m16n8k16.row.col.f32.bf16.bf16.f32 "
        "{%0,%1,%2,%3}, {%4,%5,%6,%7}, {%8,%9}, {%0,%1,%2,%3};"
        : "+f"(c[0]), "+f"(c[1]), "+f"(c[2]), "+f"(c[3])
        : "r"(a0), "r"(a1), "r"(a2), "r"(a3), "r"(b0), "r"(b1));
}

__device__ __forceinline__ void split_pack_bf16(float v0, float v1,
                                                uint32_t& hp, uint32_t& lp)
{
    __nv_bfloat16 h0 = __float2bfloat16_rn(v0);
    __nv_bfloat16 h1 = __float2bfloat16_rn(v1);
    __nv_bfloat16 l0 = __float2bfloat16_rn(v0 - __bfloat162float(h0));
    __nv_bfloat16 l1 = __float2bfloat16_rn(v1 - __bfloat162float(h1));
    __nv_bfloat162 hv = __halves2bfloat162(h0, h1);
    __nv_bfloat162 lv = __halves2bfloat162(l0, l1);
    hp = *(uint32_t*)&hv;
    lp = *(uint32_t*)&lv;
}

__device__ __forceinline__ void cp_async16(uint32_t s, const void* g) {
    asm volatile("cp.async.cg.shared.global [%0], [%1], 16;" :: "r"(s), "l"(g));
}
#define CP_COMMIT() asm volatile("cp.async.commit_group;")
#define CP_WAIT1()  asm volatile("cp.async.wait_group 1;")
#define CP_WAIT0()  asm volatile("cp.async.wait_group 0;")

// ---------------------------------------------------------------------------
// 0) sin/cos table
// ---------------------------------------------------------------------------
__global__ void init_tab_kernel() {
    int id = blockIdx.x * blockDim.x + threadIdx.x;
    if (id >= S_ * 16) return;
    int s = id >> 4;
    int j = id & 15;
    float invf = (float)pow(10000.0, -(double)j / 16.0);
    double ang = (double)s * (double)invf;
    g_sin[id] = (float)sin(ang);
    g_cos[id] = (float)cos(ang);
}

// ---------------------------------------------------------------------------
// 1+4) bf16 3-term split GEMM (m16n8k16), fp32-accurate to ~1.5e-5.
// ---------------------------------------------------------------------------
template<int KDIM, bool BIAS, bool ROPE>
__global__ __launch_bounds__(256) void gemm_bf16_kernel(
    const float* __restrict__ W, const float* __restrict__ X,
    const float* __restrict__ bias, float* __restrict__ C, int Mtot)
{
    __shared__ uint32_t Ah[8 * 72], Al[8 * 72];
    __shared__ uint32_t Bh[8 * 136], Bl[8 * 136];

    const int tid  = threadIdx.x;
    const int lane = tid & 31, warp = tid >> 5;
    const int g = lane >> 2, tg = lane & 3;
    const int wm = warp & 1, wn = warp >> 1;
    const int mbase = wm * 32, nbase = wn * 32;

    const int s0 = blockIdx.x * 128;
    const int o0 = blockIdx.y * 64;
    const int b  = blockIdx.z;

    const float* Wp = W + (size_t)o0 * KDIM;
    const float* Xp = X + (size_t)b * KDIM * S_ + s0;

    const int am = tid >> 2, akq = tid & 3;
    const int bp = tid >> 5, bnq = tid & 31;

    float4 w4  = *(const float4*)(Wp + (size_t)am * KDIM + akq * 4);
    float4 x4a = *(const float4*)(Xp + (size_t)(2 * bp) * S_ + bnq * 4);
    float4 x4b = *(const float4*)(Xp + (size_t)(2 * bp + 1) * S_ + bnq * 4);

    float acc[2][4][4] = {};

    for (int k0 = 0; k0 < KDIM; k0 += 16) {
        __syncthreads();
        {
            uint32_t hp, lp;
            split_pack_bf16(w4.x, w4.y, hp, lp);
            Ah[(2 * akq + 0) * 72 + am] = hp; Al[(2 * akq + 0) * 72 + am] = lp;
            split_pack_bf16(w4.z, w4.w, hp, lp);
            Ah[(2 * akq + 1) * 72 + am] = hp; Al[(2 * akq + 1) * 72 + am] = lp;
            uint32_t h0, l0, h1, l1, h2, l2, h3, l3;
            split_pack_bf16(x4a.x, x4b.x, h0, l0);
            split_pack_bf16(x4a.y, x4b.y, h1, l1);
            split_pack_bf16(x4a.z, x4b.z, h2, l2);
            split_pack_bf16(x4a.w, x4b.w, h3, l3);
            *(uint4*)&Bh[bp * 136 + bnq * 4] = make_uint4(h0, h1, h2, h3);
            *(uint4*)&Bl[bp * 136 + bnq * 4] = make_uint4(l0, l1, l2, l3);
        }
        __syncthreads();

        if (k0 + 16 < KDIM) {
            w4  = *(const float4*)(Wp + (size_t)am * KDIM + k0 + 16 + akq * 4);
            x4a = *(const float4*)(Xp + (size_t)(k0 + 16 + 2 * bp) * S_ + bnq * 4);
            x4b = *(const float4*)(Xp + (size_t)(k0 + 16 + 2 * bp + 1) * S_ + bnq * 4);
        }

        uint32_t ah[2][4], al[2][4];
#pragma unroll
        for (int mt = 0; mt < 2; mt++) {
            int r = mbase + mt * 16 + g;
            ah[mt][0] = Ah[tg * 72 + r];
            ah[mt][1] = Ah[tg * 72 + r + 8];
            ah[mt][2] = Ah[(tg + 4) * 72 + r];
            ah[mt][3] = Ah[(tg + 4) * 72 + r + 8];
            al[mt][0] = Al[tg * 72 + r];
            al[mt][1] = Al[tg * 72 + r + 8];
            al[mt][2] = Al[(tg + 4) * 72 + r];
            al[mt][3] = Al[(tg + 4) * 72 + r + 8];
        }
        uint32_t bh[4][2], bl[4][2];
#pragma unroll
        for (int nt = 0; nt < 4; nt++) {
            int n = nbase + nt * 8 + g;
            bh[nt][0] = Bh[tg * 136 + n];
            bh[nt][1] = Bh[(tg + 4) * 136 + n];
            bl[nt][0] = Bl[tg * 136 + n];
            bl[nt][1] = Bl[(tg + 4) * 136 + n];
        }
#pragma unroll
        for (int mt = 0; mt < 2; mt++)
#pragma unroll
            for (int nt = 0; nt < 4; nt++) {
                mma_bf16(acc[mt][nt], ah[mt][0], ah[mt][1], ah[mt][2], ah[mt][3], bh[nt][0], bh[nt][1]);
                mma_bf16(acc[mt][nt], ah[mt][0], ah[mt][1], ah[mt][2], ah[mt][3], bl[nt][0], bl[nt][1]);
                mma_bf16(acc[mt][nt], al[mt][0], al[mt][1], al[mt][2], al[mt][3], bh[nt][0], bh[nt][1]);
            }
    }

    if (ROPE && o0 < 2 * HID_ && wm == 0) {
#pragma unroll
        for (int rh = 0; rh < 2; rh++) {
            int d = rh * 8 + g;
#pragma unroll
            for (int nt = 0; nt < 4; nt++)
#pragma unroll
                for (int cl = 0; cl < 2; cl++) {
                    int col = s0 + nbase + nt * 8 + tg * 2 + cl;
                    float cs = g_cos[col * 16 + d];
                    float sn = g_sin[col * 16 + d];
                    float x = acc[0][nt][rh * 2 + cl];
                    float y = acc[1][nt][rh * 2 + cl];
                    acc[0][nt][rh * 2 + cl] = x * cs - y * sn;
                    acc[1][nt][rh * 2 + cl] = y * cs + x * sn;
                }
        }
    }

    float* Cp = C + ((size_t)b * Mtot + o0) * S_ + s0;
#pragma unroll
    for (int mt = 0; mt < 2; mt++)
#pragma unroll
        for (int rh = 0; rh < 2; rh++) {
            int row = mbase + mt * 16 + rh * 8 + g;
            float bv = BIAS ? bias[o0 + row] : 0.f;
#pragma unroll
            for (int nt = 0; nt < 4; nt++) {
                int col = nbase + nt * 8 + tg * 2;
                float2 v2 = make_float2(acc[mt][nt][rh * 2 + 0] + bv,
                                        acc[mt][nt][rh * 2 + 1] + bv);
                *(float2*)(Cp + (size_t)row * S_ + col) = v2;
            }
        }
}

// ---------------------------------------------------------------------------
// 2b) L2 norm over the sequence axis
// ---------------------------------------------------------------------------
__global__ __launch_bounds__(256) void l2norm_kernel(float* __restrict__ qkv)
{
    int row = blockIdx.x;
    int b = row >> 10;
    int o = row & 1023;
    float* p = qkv + ((size_t)b * O1_ + o) * S_;

    int tid = threadIdx.x;
    float4 v = *(float4*)(p + tid * 4);
    float ss = v.x * v.x + v.y * v.y + v.z * v.z + v.w * v.w;
#pragma unroll
    for (int off = 16; off; off >>= 1)
        ss += __shfl_xor_sync(0xffffffffu, ss, off);

    __shared__ float wss[8];
    if ((tid & 31) == 0) wss[tid >> 5] = ss;
    __syncthreads();
    if (tid < 32) {
        float t = (tid < 8) ? wss[tid] : 0.f;
#pragma unroll
        for (int off = 4; off; off >>= 1)
            t += __shfl_xor_sync(0xffffffffu, t, off);
        if (tid == 0) wss[0] = t;
    }
    __syncthreads();

    float inv = 1.0f / fmaxf(sqrtf(wss[0]), 1e-12f);
    v.x *= inv; v.y *= inv; v.z *= inv; v.w *= inv;
    *(float4*)(p + tid * 4) = v;
}

// ---------------------------------------------------------------------------
// 3) Attention: one 512-thread block/SM, Q fragments hoisted to registers.
//    16 warps = 4 i-quarters (16 rows) x 4 j-slices (16 cols).
//    Per warp-iter: 64 LDS (K 32 + V 32, Q = 0) + 32 MMA.
//    Double-buffered cp.async K/V (j-tile 64), 16 iterations.
//    smem: Qs 64x72 @0 (Q dead after hoist; reused as Ot stride 68),
//          K0/K1 64x72, V0/V1 64x68, L 64 -> 22592 floats = 88 KB.
// ---------------------------------------------------------------------------
#define AT_QS 0            // 64*72 = 4608
#define AT_K0 4608
#define AT_K1 9216
#define AT_V0 13824        // 64*68 = 4352
#define AT_V1 18176
#define AT_L  22528        // 64
#define AT_SMEM_FLOATS 22592

__global__ __launch_bounds__(512, 1) void attn_tc_kernel(
    const float* __restrict__ qkv, float* __restrict__ att)
{
    extern __shared__ float sm[];
    float* Qs  = sm + AT_QS;
    float* Lsm = sm + AT_L;

    const int tid  = threadIdx.x;
    const int lane = tid & 31;
    const int warp = tid >> 5;         // 0..15
    const int g  = lane >> 2;
    const int tg = lane & 3;
    const int wi = warp & 3;           // i-quarter (16 rows)
    const int wq = warp >> 2;          // j-slice (16 cols)
    const int ib = wi * 16;
    const int jh = wq * 16;
    const int fg = (g >> 1) | ((g & 1) << 2);   // K column permutation

    const int i0 = blockIdx.x * 64;
    const int h  = blockIdx.y;
    const int b  = blockIdx.z;

    const float* Qg = qkv + ((size_t)b * O1_ + h * D_) * S_;
    const float* Kg = Qg + (size_t)HID_ * S_;
    const float* Vg = Qg + (size_t)(2 * HID_) * S_;

    uint32_t smbase = (uint32_t)__cvta_generic_to_shared(sm);

    // K/V tile loader: 64 d-rows x 16 quads; 512 threads -> 2 rows each.
    const int ldd = tid >> 4, ljq = tid & 15;
    auto issue_kv = [&](int buf, int j0) {
        uint32_t koff = (buf ? AT_K1 : AT_K0);
        uint32_t voff = (buf ? AT_V1 : AT_V0);
#pragma unroll
        for (int r = 0; r < 2; r++) {
            int d = ldd + r * 32;
            cp_async16(smbase + (koff + d * 72 + ljq * 4) * 4,
                       Kg + (size_t)d * S_ + j0 + ljq * 4);
            cp_async16(smbase + (voff + d * 68 + ljq * 4) * 4,
                       Vg + (size_t)d * S_ + j0 + ljq * 4);
        }
    };

    // Q tile fill [d][i] stride 72, and prefetch first K/V tile.
    for (int v = tid; v < 1024; v += 512) {
        int d = v >> 4, iq = v & 15;
        *(float4*)&Qs[d * 72 + iq * 4] =
            *(const float4*)(Qg + (size_t)d * S_ + i0 + iq * 4);
    }
    issue_kv(0, 0);
    CP_COMMIT();
    if (tid < 64) Lsm[tid] = 0.f;
    __syncthreads();

    // Hoist Q fragments (loop-invariant): 32 regs. Qs is dead afterwards.
    uint32_t aq[8][4];
#pragma unroll
    for (int kk = 0; kk < 8; kk++) {
        const int k0 = kk * 8;
        const int r  = ib + g;
        aq[kk][0] = __float_as_uint(Qs[(k0 + tg) * 72 + r]);
        aq[kk][1] = __float_as_uint(Qs[(k0 + tg) * 72 + r + 8]);
        aq[kk][2] = __float_as_uint(Qs[(k0 + tg + 4) * 72 + r]);
        aq[kk][3] = __float_as_uint(Qs[(k0 + tg + 4) * 72 + r + 8]);
    }

    float oacc[8][4] = {};
    float l_acc[2]   = {0.f, 0.f};

    for (int it = 0; it < 16; it++) {
        const int cur = it & 1;
        __syncthreads();   // all warps done with buf cur^1 (about to refill)
        if (it + 1 < 16) {
            issue_kv(cur ^ 1, (it + 1) * 64);
            CP_COMMIT();
            CP_WAIT1();    // buf cur landed; next group stays in flight
        } else {
            CP_WAIT0();
        }
        __syncthreads();   // buf cur visible

        const float* Ks = sm + (cur ? AT_K1 : AT_K0);
        const float* Vs = sm + (cur ? AT_V1 : AT_V0);

        // ---- S phase: S[16 i][16 j] per warp (K columns permuted by fg)
        float sacc[2][4] = {};
#pragma unroll
        for (int kk = 0; kk < 8; kk++) {
            const int k0 = kk * 8;
            uint32_t bb[2][2];
#pragma unroll
            for (int nt = 0; nt < 2; nt++) {
                int jc = jh + nt * 8 + fg;
                bb[nt][0] = __float_as_uint(Ks[(k0 + tg) * 72 + jc]);
                bb[nt][1] = __float_as_uint(Ks[(k0 + tg + 4) * 72 + jc]);
            }
#pragma unroll
            for (int nt = 0; nt < 2; nt++)
                mma_tf32(sacc[nt], aq[kk][0], aq[kk][1], aq[kk][2], aq[kk][3],
                         bb[nt][0], bb[nt][1]);
        }

        // ---- exp in place + row sums (j-permutation is sum-invariant)
#pragma unroll
        for (int nt = 0; nt < 2; nt++) {
            float p0 = __expf(10.f * sacc[nt][0]);
            float p1 = __expf(10.f * sacc[nt][1]);
            float p2 = __expf(10.f * sacc[nt][2]);
            float p3 = __expf(10.f * sacc[nt][3]);
            sacc[nt][0] = p0; sacc[nt][1] = p1;
            sacc[nt][2] = p2; sacc[nt][3] = p3;
            l_acc[0] += p0 + p1;    // row g
            l_acc[1] += p2 + p3;    // row g+8
        }

        // ---- O phase: P (registers) x V^T, n = all 64 d, k = 16 j
#pragma unroll
        for (int ks = 0; ks < 2; ks++) {
            const int jk = jh + ks * 8;
            uint32_t bb[8][2];
#pragma unroll
            for (int nt = 0; nt < 8; nt++) {
                int dc = nt * 8 + g;
                bb[nt][0] = __float_as_uint(Vs[dc * 68 + jk + tg]);
                bb[nt][1] = __float_as_uint(Vs[dc * 68 + jk + tg + 4]);
            }
            uint32_t a0 = __float_as_uint(sacc[ks][0]);
            uint32_t a1 = __float_as_uint(sacc[ks][2]);
            uint32_t a2 = __float_as_uint(sacc[ks][1]);
            uint32_t a3 = __float_as_uint(sacc[ks][3]);
#pragma unroll
            for (int nt = 0; nt < 8; nt++)
                mma_tf32(oacc[nt], a0, a1, a2, a3, bb[nt][0], bb[nt][1]);
        }
    }

    // ---- row sums: reduce over tg lanes, merge 4 j-warps via atomicAdd
#pragma unroll
    for (int rh = 0; rh < 2; rh++) {
        float l = l_acc[rh];
        l += __shfl_xor_sync(0xffffffffu, l, 1);
        l += __shfl_xor_sync(0xffffffffu, l, 2);
        if (tg == 0)
            atomicAdd(&Lsm[ib + rh * 8 + g], l);
    }
    __syncthreads();

    // ---- staged reduction of partial O across 4 j-warps into Ot=Qs (str 68)
#pragma unroll
    for (int r = 0; r < 4; r++) {
        if (wq == r) {
#pragma unroll
            for (int nt = 0; nt < 8; nt++)
#pragma unroll
                for (int c = 0; c < 4; c++) {
                    int row = ib + g + ((c >> 1) << 3);
                    int col = nt * 8 + tg * 2 + (c & 1);
                    if (r == 0) Qs[col * 68 + row] = oacc[nt][c];
                    else        Qs[col * 68 + row] += oacc[nt][c];
                }
        }
        __syncthreads();
    }

    if (tid < 64) Lsm[tid] = 1.0f / Lsm[tid];
    __syncthreads();

    // ---- normalized, coalesced store [d][s]
    float* Ap = att + ((size_t)b * HID_ + h * D_) * S_ + i0;
    for (int v = tid; v < 1024; v += 512) {
        int d = v >> 4, iq = v & 15;
        float4 o = *(float4*)&Qs[d * 68 + iq * 4];
        o.x *= Lsm[iq * 4 + 0];
        o.y *= Lsm[iq * 4 + 1];
        o.z *= Lsm[iq * 4 + 2];
        o.w *= Lsm[iq * 4 + 3];
        *(float4*)(Ap + (size_t)d * S_ + iq * 4) = o;
    }
}

// ---------------------------------------------------------------------------
// Launch
// ---------------------------------------------------------------------------
extern "C" void kernel_launch(void* const* d_in, const int* in_sizes, int n_in,
                              void* d_out, int out_size)
{
    const float* x     = (const float*)d_in[0];
    const float* w_qkv = (const float*)d_in[1];
    const float* w_out = (const float*)d_in[2];
    const float* b_out = (const float*)d_in[3];
    float* out = (float*)d_out;

    float* qkv; cudaGetSymbolAddress((void**)&qkv, g_qkv);
    float* att; cudaGetSymbolAddress((void**)&att, g_att);

    static const size_t attn_smem = AT_SMEM_FLOATS * sizeof(float);  // ~88 KB
    cudaFuncSetAttribute(attn_tc_kernel,
                         cudaFuncAttributeMaxDynamicSharedMemorySize,
                         (int)attn_smem);

    init_tab_kernel<<<(S_ * 16 + 255) / 256, 256>>>();

    {   // QKV projection (bf16x3, fused RoPE on q/k tiles)
        dim3 grid(S_ / 128, O1_ / 64, B_);
        gemm_bf16_kernel<256, false, true><<<grid, 256>>>(w_qkv, x, nullptr, qkv, O1_);
    }

    l2norm_kernel<<<B_ * 2 * HID_, 256>>>(qkv);

    {   // Attention (512 threads, Q-in-registers, double-buffered cp.async)
        dim3 grid(S_ / 64, H_, B_);
        attn_tc_kernel<<<grid, 512, attn_smem>>>(qkv, att);
    }

    {   // Output projection (bf16x3 + bias)
        dim3 grid(S_ / 128, C_ / 64, B_);
        gemm_bf16_kernel<512, true, false><<<grid, 256>>>(w_out, att, b_out, out, C_);
    }
}

// round 15
// speedup vs baseline: 1.1433x; 1.1433x over previous
#include <cuda_runtime.h>
#include <cuda_bf16.h>
#include <math.h>
#include <stdint.h>

// ---------------------------------------------------------------------------
// Problem constants
//   x: (8, 256, 32, 32)  -> [b][c][s], s = 1024
//   w_qkv: (1536, 256), w_out: (256, 512), b_out: (256,)
//   HEADS=8, DIM_HEAD=64, SCALE=10, ROT_DIM=32 (16 freqs)
//   L2 norm over the SEQUENCE axis (per (b,h,d) row), per reference.
// ---------------------------------------------------------------------------
#define B_   8
#define C_   256
#define S_   1024
#define H_   8
#define D_   64
#define HID_ 512
#define O1_  1536

__device__ float    g_qkv[B_ * O1_ * S_];        // [b][o][s] fp32
__device__ float    g_sin[S_ * 16];
__device__ float    g_cos[S_ * 16];
// pre-split bf16 pair-packed operands (word = bf16x2 of k-pair)
__device__ uint32_t g_wqh[128 * O1_], g_wql[128 * O1_];   // w_qkv^T  [kp][o]
__device__ uint32_t g_woh[256 * C_],  g_wol[256 * C_];    // w_out^T  [kp][o]
__device__ uint32_t g_xh[B_ * 128 * S_], g_xl[B_ * 128 * S_];   // x   [b][kp][s]
__device__ uint32_t g_oh[B_ * 256 * S_], g_ol[B_ * 256 * S_];   // att [b][kp][s]

// ---------------------------------------------------------------------------
// MMA + pack helpers
// ---------------------------------------------------------------------------
__device__ __forceinline__ void mma_tf32(float c[4],
    uint32_t a0, uint32_t a1, uint32_t a2, uint32_t a3,
    uint32_t b0, uint32_t b1)
{
    asm volatile(
        "mma.sync.aligned.m16n8k8.row.col.f32.tf32.tf32.f32 "
        "{%0,%1,%2,%3}, {%4,%5,%6,%7}, {%8,%9}, {%0,%1,%2,%3};"
        : "+f"(c[0]), "+f"(c[1]), "+f"(c[2]), "+f"(c[3])
        : "r"(a0), "r"(a1), "r"(a2), "r"(a3), "r"(b0), "r"(b1));
}

__device__ __forceinline__ void mma_bf16(float c[4],
    uint32_t a0, uint32_t a1, uint32_t a2, uint32_t a3,
    uint32_t b0, uint32_t b1)
{
    asm volatile(
        "mma.sync.aligned.m16n8k16.row.col.f32.bf16.bf16.f32 "
        "{%0,%1,%2,%3}, {%4,%5,%6,%7}, {%8,%9}, {%0,%1,%2,%3};"
        : "+f"(c[0]), "+f"(c[1]), "+f"(c[2]), "+f"(c[3])
        : "r"(a0), "r"(a1), "r"(a2), "r"(a3), "r"(b0), "r"(b1));
}

__device__ __forceinline__ void split_pack_bf16(float v0, float v1,
                                                uint32_t& hp, uint32_t& lp)
{
    __nv_bfloat16 h0 = __float2bfloat16_rn(v0);
    __nv_bfloat16 h1 = __float2bfloat16_rn(v1);
    __nv_bfloat16 l0 = __float2bfloat16_rn(v0 - __bfloat162float(h0));
    __nv_bfloat16 l1 = __float2bfloat16_rn(v1 - __bfloat162float(h1));
    __nv_bfloat162 hv = __halves2bfloat162(h0, h1);
    __nv_bfloat162 lv = __halves2bfloat162(l0, l1);
    hp = *(uint32_t*)&hv;
    lp = *(uint32_t*)&lv;
}

__device__ __forceinline__ void cp_async16(uint32_t s, const void* g) {
    asm volatile("cp.async.cg.shared.global [%0], [%1], 16;" :: "r"(s), "l"(g));
}
#define CP_COMMIT() asm volatile("cp.async.commit_group;")
#define CP_WAIT1()  asm volatile("cp.async.wait_group 1;")
#define CP_WAIT0()  asm volatile("cp.async.wait_group 0;")

// ---------------------------------------------------------------------------
// 0) sin/cos table
// ---------------------------------------------------------------------------
__global__ void init_tab_kernel() {
    int id = blockIdx.x * blockDim.x + threadIdx.x;
    if (id >= S_ * 16) return;
    int s = id >> 4;
    int j = id & 15;
    float invf = (float)pow(10000.0, -(double)j / 16.0);
    double ang = (double)s * (double)invf;
    g_sin[id] = (float)sin(ang);
    g_cos[id] = (float)cos(ang);
}

// ---------------------------------------------------------------------------
// 0b) weight split: W[M][KD] fp32 -> Wh/Wl [KD/2][M] bf16x2 (transposed+packed)
// ---------------------------------------------------------------------------
__global__ void split_w_kernel(const float* __restrict__ W,
                               uint32_t* __restrict__ Wh, uint32_t* __restrict__ Wl,
                               int M, int KD)
{
    int id = blockIdx.x * blockDim.x + threadIdx.x;
    int KP = KD >> 1;
    if (id >= KP * M) return;
    int kp = id / M, o = id - kp * M;
    uint32_t hp, lp;
    split_pack_bf16(W[(size_t)o * KD + 2 * kp], W[(size_t)o * KD + 2 * kp + 1], hp, lp);
    Wh[id] = hp; Wl[id] = lp;
}

// ---------------------------------------------------------------------------
// 0c) x split: X[b][256][1024] -> Xh/Xl [b][128][1024] bf16x2 (k-pair packed)
// ---------------------------------------------------------------------------
__global__ __launch_bounds__(256) void split_x_kernel(const float* __restrict__ X,
                                                      uint32_t* __restrict__ Xh,
                                                      uint32_t* __restrict__ Xl)
{
    int id = blockIdx.x * blockDim.x + threadIdx.x;   // 8*128*256
    int s4 = (id & 255) * 4;
    int kp = (id >> 8) & 127;
    int b  = id >> 15;
    float4 v0 = *(const float4*)(X + ((size_t)b * 256 + 2 * kp) * S_ + s4);
    float4 v1 = *(const float4*)(X + ((size_t)b * 256 + 2 * kp + 1) * S_ + s4);
    uint32_t h0, l0, h1, l1, h2, l2, h3, l3;
    split_pack_bf16(v0.x, v1.x, h0, l0);
    split_pack_bf16(v0.y, v1.y, h1, l1);
    split_pack_bf16(v0.z, v1.z, h2, l2);
    split_pack_bf16(v0.w, v1.w, h3, l3);
    size_t oidx = ((size_t)b * 128 + kp) * S_ + s4;
    *(uint4*)(Xh + oidx) = make_uint4(h0, h1, h2, h3);
    *(uint4*)(Xl + oidx) = make_uint4(l0, l1, l2, l3);
}

// ---------------------------------------------------------------------------
// 1+4) bf16 3-term GEMM on PRE-SPLIT operands, cp.async double-buffered.
//      C[b, o0+m, s0+n] = sum_k W[m][k]*X[k][n] (+bias) (+rope on q/k tiles)
//      Block 64m x 128n, 8 warps (2m x 4n), chunk = 8 kpairs (k16).
//      smem words: A [8][72], B [8][136] x {h,l} x {2 buf} = 26 KB.
// ---------------------------------------------------------------------------
#define GA_H0 0            // 8*72 = 576
#define GA_H1 576
#define GA_L0 1152
#define GA_L1 1728
#define GB_H0 2304         // 8*136 = 1088
#define GB_H1 3392
#define GB_L0 4480
#define GB_L1 5568
#define G_SMEM_WORDS 6656

template<int KDIM, bool BIAS, bool ROPE>
__global__ __launch_bounds__(256) void gemm_pre_kernel(
    const uint32_t* __restrict__ Wh, const uint32_t* __restrict__ Wl,
    const uint32_t* __restrict__ Xh, const uint32_t* __restrict__ Xl,
    const float* __restrict__ bias, float* __restrict__ C, int Mtot)
{
    constexpr int KP = KDIM / 2;
    constexpr int NC = KDIM / 16;    // chunks of 8 kpairs

    __shared__ uint32_t smg[G_SMEM_WORDS];

    const int tid  = threadIdx.x;
    const int lane = tid & 31, warp = tid >> 5;
    const int g = lane >> 2, tg = lane & 3;
    const int wm = warp & 1, wn = warp >> 1;
    const int mbase = wm * 32, nbase = wn * 32;

    const int s0 = blockIdx.x * 128;
    const int o0 = blockIdx.y * 64;
    const int b  = blockIdx.z;

    uint32_t smbase = (uint32_t)__cvta_generic_to_shared(smg);

    // loaders
    const int ar = (tid & 127) >> 4;        // A row 0..7
    const int aq = tid & 15;                // A quad
    const bool alo = tid >= 128;            // half threads: Ah vs Al
    const int br = tid >> 5;                // B row 0..7
    const int bq = tid & 31;                // B quad

    const uint32_t* Wsrc = alo ? Wl : Wh;
    const uint32_t* XhB = Xh + (size_t)b * KP * S_ + s0;
    const uint32_t* XlB = Xl + (size_t)b * KP * S_ + s0;

    auto issue = [&](int chunk, int buf) {
        int kp0 = chunk * 8;
        uint32_t aoff = alo ? (buf ? GA_L1 : GA_L0) : (buf ? GA_H1 : GA_H0);
        cp_async16(smbase + (aoff + ar * 72 + aq * 4) * 4,
                   Wsrc + (size_t)(kp0 + ar) * Mtot + o0 + aq * 4);
        uint32_t bhoff = buf ? GB_H1 : GB_H0;
        uint32_t bloff = buf ? GB_L1 : GB_L0;
        cp_async16(smbase + (bhoff + br * 136 + bq * 4) * 4,
                   XhB + (size_t)(kp0 + br) * S_ + bq * 4);
        cp_async16(smbase + (bloff + br * 136 + bq * 4) * 4,
                   XlB + (size_t)(kp0 + br) * S_ + bq * 4);
    };

    issue(0, 0);
    CP_COMMIT();

    float acc[2][4][4] = {};

    for (int c = 0; c < NC; c++) {
        const int cur = c & 1;
        if (c + 1 < NC) {
            issue(c + 1, cur ^ 1);
            CP_COMMIT();
            CP_WAIT1();
        } else {
            CP_WAIT0();
        }
        __syncthreads();   // buf cur ready for all warps

        const uint32_t* AhP = smg + (cur ? GA_H1 : GA_H0);
        const uint32_t* AlP = smg + (cur ? GA_L1 : GA_L0);
        const uint32_t* BhP = smg + (cur ? GB_H1 : GB_H0);
        const uint32_t* BlP = smg + (cur ? GB_L1 : GB_L0);

        uint32_t ah[2][4], al[2][4];
#pragma unroll
        for (int mt = 0; mt < 2; mt++) {
            int r = mbase + mt * 16 + g;
            ah[mt][0] = AhP[tg * 72 + r];
            ah[mt][1] = AhP[tg * 72 + r + 8];
            ah[mt][2] = AhP[(tg + 4) * 72 + r];
            ah[mt][3] = AhP[(tg + 4) * 72 + r + 8];
            al[mt][0] = AlP[tg * 72 + r];
            al[mt][1] = AlP[tg * 72 + r + 8];
            al[mt][2] = AlP[(tg + 4) * 72 + r];
            al[mt][3] = AlP[(tg + 4) * 72 + r + 8];
        }
        uint32_t bh[4][2], bl[4][2];
#pragma unroll
        for (int nt = 0; nt < 4; nt++) {
            int n = nbase + nt * 8 + g;
            bh[nt][0] = BhP[tg * 136 + n];
            bh[nt][1] = BhP[(tg + 4) * 136 + n];
            bl[nt][0] = BlP[tg * 136 + n];
            bl[nt][1] = BlP[(tg + 4) * 136 + n];
        }
#pragma unroll
        for (int mt = 0; mt < 2; mt++)
#pragma unroll
            for (int nt = 0; nt < 4; nt++) {
                mma_bf16(acc[mt][nt], ah[mt][0], ah[mt][1], ah[mt][2], ah[mt][3], bh[nt][0], bh[nt][1]);
                mma_bf16(acc[mt][nt], ah[mt][0], ah[mt][1], ah[mt][2], ah[mt][3], bl[nt][0], bl[nt][1]);
                mma_bf16(acc[mt][nt], al[mt][0], al[mt][1], al[mt][2], al[mt][3], bh[nt][0], bh[nt][1]);
            }
        __syncthreads();   // all reads of buf cur done before its refill
    }

    if (ROPE && o0 < 2 * HID_ && wm == 0) {
#pragma unroll
        for (int rh = 0; rh < 2; rh++) {
            int d = rh * 8 + g;
#pragma unroll
            for (int nt = 0; nt < 4; nt++)
#pragma unroll
                for (int cl = 0; cl < 2; cl++) {
                    int col = s0 + nbase + nt * 8 + tg * 2 + cl;
                    float cs = g_cos[col * 16 + d];
                    float sn = g_sin[col * 16 + d];
                    float x = acc[0][nt][rh * 2 + cl];
                    float y = acc[1][nt][rh * 2 + cl];
                    acc[0][nt][rh * 2 + cl] = x * cs - y * sn;
                    acc[1][nt][rh * 2 + cl] = y * cs + x * sn;
                }
        }
    }

    float* Cp = C + ((size_t)b * Mtot + o0) * S_ + s0;
#pragma unroll
    for (int mt = 0; mt < 2; mt++)
#pragma unroll
        for (int rh = 0; rh < 2; rh++) {
            int row = mbase + mt * 16 + rh * 8 + g;
            float bv = BIAS ? bias[o0 + row] : 0.f;
#pragma unroll
            for (int nt = 0; nt < 4; nt++) {
                int col = nbase + nt * 8 + tg * 2;
                float2 v2 = make_float2(acc[mt][nt][rh * 2 + 0] + bv,
                                        acc[mt][nt][rh * 2 + 1] + bv);
                *(float2*)(Cp + (size_t)row * S_ + col) = v2;
            }
        }
}

// ---------------------------------------------------------------------------
// 2b) L2 norm over the sequence axis (in-place on fp32 qkv)
// ---------------------------------------------------------------------------
__global__ __launch_bounds__(256) void l2norm_kernel(float* __restrict__ qkv)
{
    int row = blockIdx.x;
    int b = row >> 10;
    int o = row & 1023;
    float* p = qkv + ((size_t)b * O1_ + o) * S_;

    int tid = threadIdx.x;
    float4 v = *(float4*)(p + tid * 4);
    float ss = v.x * v.x + v.y * v.y + v.z * v.z + v.w * v.w;
#pragma unroll
    for (int off = 16; off; off >>= 1)
        ss += __shfl_xor_sync(0xffffffffu, ss, off);

    __shared__ float wss[8];
    if ((tid & 31) == 0) wss[tid >> 5] = ss;
    __syncthreads();
    if (tid < 32) {
        float t = (tid < 8) ? wss[tid] : 0.f;
#pragma unroll
        for (int off = 4; off; off >>= 1)
            t += __shfl_xor_sync(0xffffffffu, t, off);
        if (tid == 0) wss[0] = t;
    }
    __syncthreads();

    float inv = 1.0f / fmaxf(sqrtf(wss[0]), 1e-12f);
    v.x *= inv; v.y *= inv; v.z *= inv; v.w *= inv;
    *(float4*)(p + tid * 4) = v;
}

// ---------------------------------------------------------------------------
// 3) Attention (R12 config — best known): 2 blocks/SM, double-buffered
//    cp.async K/V (j-tile 64), register-resident P, staged O reduction.
//    Epilogue now writes output as packed bf16 hi/lo pairs (d-pairs) feeding
//    the out-projection GEMM directly.
// ---------------------------------------------------------------------------
#define AT_QS 0            // 64*72 = 4608
#define AT_K0 4608
#define AT_K1 9216
#define AT_V0 13824        // 64*68 = 4352
#define AT_V1 18176
#define AT_L  22528        // 64
#define AT_SMEM_FLOATS 22592

__global__ __launch_bounds__(256, 2) void attn_tc_kernel(
    const float* __restrict__ qkv,
    uint32_t* __restrict__ Oh, uint32_t* __restrict__ Ol)
{
    extern __shared__ float sm[];
    float* Qs  = sm + AT_QS;
    float* Lsm = sm + AT_L;

    const int tid  = threadIdx.x;
    const int lane = tid & 31;
    const int warp = tid >> 5;
    const int g  = lane >> 2;
    const int tg = lane & 3;
    const int wi = warp & 1;
    const int wq = warp >> 1;          // 0..3: 16-j slice
    const int ib = wi * 32;
    const int jh = wq * 16;
    const int fg = (g >> 1) | ((g & 1) << 2);   // K column permutation

    const int i0 = blockIdx.x * 64;
    const int h  = blockIdx.y;
    const int b  = blockIdx.z;

    const float* Qg = qkv + ((size_t)b * O1_ + h * D_) * S_;
    const float* Kg = Qg + (size_t)HID_ * S_;
    const float* Vg = Qg + (size_t)(2 * HID_) * S_;

    uint32_t smbase = (uint32_t)__cvta_generic_to_shared(sm);

    // Q tile [d][i], stride 72
    for (int v = tid; v < 1024; v += 256) {
        int d = v >> 4, iq = v & 15;
        *(float4*)&Qs[d * 72 + iq * 4] =
            *(const float4*)(Qg + (size_t)d * S_ + i0 + iq * 4);
    }
    if (tid < 64) Lsm[tid] = 0.f;

    const int ldd = tid >> 4, ljq = tid & 15;
    auto issue_kv = [&](int buf, int j0) {
        uint32_t koff = (buf ? AT_K1 : AT_K0);
        uint32_t voff = (buf ? AT_V1 : AT_V0);
#pragma unroll
        for (int r = 0; r < 4; r++) {
            int d = ldd + r * 16;
            cp_async16(smbase + (koff + d * 72 + ljq * 4) * 4,
                       Kg + (size_t)d * S_ + j0 + ljq * 4);
            cp_async16(smbase + (voff + d * 68 + ljq * 4) * 4,
                       Vg + (size_t)d * S_ + j0 + ljq * 4);
        }
    };

    issue_kv(0, 0);
    CP_COMMIT();

    float oacc[2][8][4] = {};
    float l_acc[2][2]   = {};

    for (int it = 0; it < 16; it++) {
        const int cur = it & 1;
        __syncthreads();
        if (it + 1 < 16) {
            issue_kv(cur ^ 1, (it + 1) * 64);
            CP_COMMIT();
            CP_WAIT1();
        } else {
            CP_WAIT0();
        }
        __syncthreads();

        const float* Ks = sm + (cur ? AT_K1 : AT_K0);
        const float* Vs = sm + (cur ? AT_V1 : AT_V0);

        // ---- S phase: S[32 i][16 j] per warp (K columns permuted by fg)
        float sacc[2][2][4] = {};
#pragma unroll
        for (int kk = 0; kk < 8; kk++) {
            const int k0 = kk * 8;
            uint32_t a[2][4];
#pragma unroll
            for (int mt = 0; mt < 2; mt++) {
                int r = ib + mt * 16 + g;
                a[mt][0] = __float_as_uint(Qs[(k0 + tg) * 72 + r]);
                a[mt][1] = __float_as_uint(Qs[(k0 + tg) * 72 + r + 8]);
                a[mt][2] = __float_as_uint(Qs[(k0 + tg + 4) * 72 + r]);
                a[mt][3] = __float_as_uint(Qs[(k0 + tg + 4) * 72 + r + 8]);
            }
            uint32_t bb[2][2];
#pragma unroll
            for (int nt = 0; nt < 2; nt++) {
                int jc = jh + nt * 8 + fg;
                bb[nt][0] = __float_as_uint(Ks[(k0 + tg) * 72 + jc]);
                bb[nt][1] = __float_as_uint(Ks[(k0 + tg + 4) * 72 + jc]);
            }
#pragma unroll
            for (int mt = 0; mt < 2; mt++)
#pragma unroll
                for (int nt = 0; nt < 2; nt++)
                    mma_tf32(sacc[mt][nt], a[mt][0], a[mt][1], a[mt][2], a[mt][3],
                             bb[nt][0], bb[nt][1]);
        }

        // ---- exp in place + row sums
#pragma unroll
        for (int mt = 0; mt < 2; mt++)
#pragma unroll
            for (int nt = 0; nt < 2; nt++) {
                float p0 = __expf(10.f * sacc[mt][nt][0]);
                float p1 = __expf(10.f * sacc[mt][nt][1]);
                float p2 = __expf(10.f * sacc[mt][nt][2]);
                float p3 = __expf(10.f * sacc[mt][nt][3]);
                sacc[mt][nt][0] = p0; sacc[mt][nt][1] = p1;
                sacc[mt][nt][2] = p2; sacc[mt][nt][3] = p3;
                l_acc[mt][0] += p0 + p1;
                l_acc[mt][1] += p2 + p3;
            }

        // ---- O phase: P (registers) x V^T, n = all 64 d, k = 16 j
#pragma unroll
        for (int ks = 0; ks < 2; ks++) {
            const int jk = jh + ks * 8;
            uint32_t bb[8][2];
#pragma unroll
            for (int nt = 0; nt < 8; nt++) {
                int dc = nt * 8 + g;
                bb[nt][0] = __float_as_uint(Vs[dc * 68 + jk + tg]);
                bb[nt][1] = __float_as_uint(Vs[dc * 68 + jk + tg + 4]);
            }
#pragma unroll
            for (int mt = 0; mt < 2; mt++) {
                uint32_t a0 = __float_as_uint(sacc[mt][ks][0]);
                uint32_t a1 = __float_as_uint(sacc[mt][ks][2]);
                uint32_t a2 = __float_as_uint(sacc[mt][ks][1]);
                uint32_t a3 = __float_as_uint(sacc[mt][ks][3]);
#pragma unroll
                for (int nt = 0; nt < 8; nt++)
                    mma_tf32(oacc[mt][nt], a0, a1, a2, a3, bb[nt][0], bb[nt][1]);
            }
        }
    }

    // ---- row sums: reduce over tg lanes, merge 4 j-warps via atomicAdd
#pragma unroll
    for (int mt = 0; mt < 2; mt++)
#pragma unroll
        for (int rh = 0; rh < 2; rh++) {
            float l = l_acc[mt][rh];
            l += __shfl_xor_sync(0xffffffffu, l, 1);
            l += __shfl_xor_sync(0xffffffffu, l, 2);
            if (tg == 0)
                atomicAdd(&Lsm[ib + mt * 16 + rh * 8 + g], l);
        }
    __syncthreads();

    // ---- staged reduction of partial O across 4 j-warps into Ot=Qs (str 68)
#pragma unroll
    for (int r = 0; r < 4; r++) {
        if (wq == r) {
#pragma unroll
            for (int mt = 0; mt < 2; mt++)
#pragma unroll
                for (int nt = 0; nt < 8; nt++)
#pragma unroll
                    for (int c = 0; c < 4; c++) {
                        int row = ib + mt * 16 + g + ((c >> 1) << 3);
                        int col = nt * 8 + tg * 2 + (c & 1);
                        if (r == 0) Qs[col * 68 + row] = oacc[mt][nt][c];
                        else        Qs[col * 68 + row] += oacc[mt][nt][c];
                    }
        }
        __syncthreads();
    }

    if (tid < 64) Lsm[tid] = 1.0f / Lsm[tid];
    __syncthreads();

    // ---- normalized store as packed bf16 hi/lo d-pairs: O[b][kp][s]
    //      kp = h*32 + p, pair = (d=2p, d=2p+1); coalesced uint4 writes.
    for (int v = tid; v < 512; v += 256) {
        int p = v >> 4, iq = v & 15;
        float4 o0 = *(float4*)&Qs[(2 * p) * 68 + iq * 4];
        float4 o1 = *(float4*)&Qs[(2 * p + 1) * 68 + iq * 4];
        float i0s = Lsm[iq * 4 + 0], i1s = Lsm[iq * 4 + 1];
        float i2s = Lsm[iq * 4 + 2], i3s = Lsm[iq * 4 + 3];
        o0.x *= i0s; o0.y *= i1s; o0.z *= i2s; o0.w *= i3s;
        o1.x *= i0s; o1.y *= i1s; o1.z *= i2s; o1.w *= i3s;
        uint32_t h0, l0, h1, l1, h2, l2, h3, l3;
        split_pack_bf16(o0.x, o1.x, h0, l0);
        split_pack_bf16(o0.y, o1.y, h1, l1);
        split_pack_bf16(o0.z, o1.z, h2, l2);
        split_pack_bf16(o0.w, o1.w, h3, l3);
        size_t oidx = ((size_t)b * 256 + h * 32 + p) * S_ + i0 + iq * 4;
        *(uint4*)(Oh + oidx) = make_uint4(h0, h1, h2, h3);
        *(uint4*)(Ol + oidx) = make_uint4(l0, l1, l2, l3);
    }
}

// ---------------------------------------------------------------------------
// Launch
// ---------------------------------------------------------------------------
extern "C" void kernel_launch(void* const* d_in, const int* in_sizes, int n_in,
                              void* d_out, int out_size)
{
    const float* x     = (const float*)d_in[0];
    const float* w_qkv = (const float*)d_in[1];
    const float* w_out = (const float*)d_in[2];
    const float* b_out = (const float*)d_in[3];
    float* out = (float*)d_out;

    float* qkv;   cudaGetSymbolAddress((void**)&qkv, g_qkv);
    uint32_t *wqh, *wql, *woh, *wol, *xh, *xl, *oh, *ol;
    cudaGetSymbolAddress((void**)&wqh, g_wqh);
    cudaGetSymbolAddress((void**)&wql, g_wql);
    cudaGetSymbolAddress((void**)&woh, g_woh);
    cudaGetSymbolAddress((void**)&wol, g_wol);
    cudaGetSymbolAddress((void**)&xh, g_xh);
    cudaGetSymbolAddress((void**)&xl, g_xl);
    cudaGetSymbolAddress((void**)&oh, g_oh);
    cudaGetSymbolAddress((void**)&ol, g_ol);

    static const size_t attn_smem = AT_SMEM_FLOATS * sizeof(float);  // ~88 KB
    cudaFuncSetAttribute(attn_tc_kernel,
                         cudaFuncAttributeMaxDynamicSharedMemorySize,
                         (int)attn_smem);

    init_tab_kernel<<<(S_ * 16 + 255) / 256, 256>>>();

    // prep: split+pack weights and x to bf16 hi/lo
    split_w_kernel<<<(128 * O1_ + 255) / 256, 256>>>(w_qkv, wqh, wql, O1_, 256);
    split_w_kernel<<<(256 * C_ + 255) / 256, 256>>>(w_out, woh, wol, C_, 512);
    split_x_kernel<<<(B_ * 128 * 256) / 256, 256>>>(x, xh, xl);

    {   // QKV projection (pre-split bf16x3, fused RoPE on q/k tiles)
        dim3 grid(S_ / 128, O1_ / 64, B_);
        gemm_pre_kernel<256, false, true><<<grid, 256>>>(wqh, wql, xh, xl,
                                                         nullptr, qkv, O1_);
    }

    l2norm_kernel<<<B_ * 2 * HID_, 256>>>(qkv);

    {   // Attention (R12 config; writes packed bf16 hi/lo output)
        dim3 grid(S_ / 64, H_, B_);
        attn_tc_kernel<<<grid, 256, attn_smem>>>(qkv, oh, ol);
    }

    {   // Output projection (pre-split bf16x3 + bias)
        dim3 grid(S_ / 128, C_ / 64, B_);
        gemm_pre_kernel<512, true, false><<<grid, 256>>>(woh, wol, oh, ol,
                                                         b_out, out, C_);
    }
}

// round 16
// speedup vs baseline: 1.2066x; 1.0553x over previous
#include <cuda_runtime.h>
#include <cuda_bf16.h>
#include <math.h>
#include <stdint.h>

// ---------------------------------------------------------------------------
// Problem constants
// ---------------------------------------------------------------------------
#define B_   8
#define C_   256
#define S_   1024
#define H_   8
#define D_   64
#define HID_ 512
#define O1_  1536

__device__ float    g_qkv[B_ * O1_ * S_];        // [b][o][s] fp32
__device__ float    g_sin[S_ * 16];
__device__ float    g_cos[S_ * 16];
// pre-split bf16 pair-packed operands (word = bf16x2 of k-pair)
__device__ uint32_t g_wqh[128 * O1_], g_wql[128 * O1_];   // w_qkv^T  [kp][o]
__device__ uint32_t g_woh[256 * C_],  g_wol[256 * C_];    // w_out^T  [kp][o]
__device__ uint32_t g_xh[B_ * 128 * S_], g_xl[B_ * 128 * S_];   // x   [b][kp][s]
__device__ uint32_t g_oh[B_ * 256 * S_], g_ol[B_ * 256 * S_];   // att [b][kp][s]

// ---------------------------------------------------------------------------
// MMA + pack helpers
// ---------------------------------------------------------------------------
__device__ __forceinline__ void mma_tf32(float c[4],
    uint32_t a0, uint32_t a1, uint32_t a2, uint32_t a3,
    uint32_t b0, uint32_t b1)
{
    asm volatile(
        "mma.sync.aligned.m16n8k8.row.col.f32.tf32.tf32.f32 "
        "{%0,%1,%2,%3}, {%4,%5,%6,%7}, {%8,%9}, {%0,%1,%2,%3};"
        : "+f"(c[0]), "+f"(c[1]), "+f"(c[2]), "+f"(c[3])
        : "r"(a0), "r"(a1), "r"(a2), "r"(a3), "r"(b0), "r"(b1));
}

__device__ __forceinline__ void mma_bf16(float c[4],
    uint32_t a0, uint32_t a1, uint32_t a2, uint32_t a3,
    uint32_t b0, uint32_t b1)
{
    asm volatile(
        "mma.sync.aligned.m16n8k16.row.col.f32.bf16.bf16.f32 "
        "{%0,%1,%2,%3}, {%4,%5,%6,%7}, {%8,%9}, {%0,%1,%2,%3};"
        : "+f"(c[0]), "+f"(c[1]), "+f"(c[2]), "+f"(c[3])
        : "r"(a0), "r"(a1), "r"(a2), "r"(a3), "r"(b0), "r"(b1));
}

__device__ __forceinline__ void split_pack_bf16(float v0, float v1,
                                                uint32_t& hp, uint32_t& lp)
{
    __nv_bfloat16 h0 = __float2bfloat16_rn(v0);
    __nv_bfloat16 h1 = __float2bfloat16_rn(v1);
    __nv_bfloat16 l0 = __float2bfloat16_rn(v0 - __bfloat162float(h0));
    __nv_bfloat16 l1 = __float2bfloat16_rn(v1 - __bfloat162float(h1));
    __nv_bfloat162 hv = __halves2bfloat162(h0, h1);
    __nv_bfloat162 lv = __halves2bfloat162(l0, l1);
    hp = *(uint32_t*)&hv;
    lp = *(uint32_t*)&lv;
}

__device__ __forceinline__ void cp_async16(uint32_t s, const void* g) {
    asm volatile("cp.async.cg.shared.global [%0], [%1], 16;" :: "r"(s), "l"(g));
}
#define CP_COMMIT() asm volatile("cp.async.commit_group;")
#define CP_WAIT1()  asm volatile("cp.async.wait_group 1;")
#define CP_WAIT0()  asm volatile("cp.async.wait_group 0;")

// ---------------------------------------------------------------------------
// 0) fused prep: sin/cos table + weight splits + x split, dispatched by block
//    blocks: [0,64) init_tab | [64,832) split w_qkv | [832,1088) split w_out
//            | [1088,2112) split x
// ---------------------------------------------------------------------------
__global__ __launch_bounds__(256) void prep_kernel(
    const float* __restrict__ x,
    const float* __restrict__ w_qkv,
    const float* __restrict__ w_out)
{
    int blk = blockIdx.x;
    int tid = threadIdx.x;

    if (blk < 64) {                              // sin/cos (16384 entries)
        int id = blk * 256 + tid;
        int s = id >> 4;
        int j = id & 15;
        float invf = (float)pow(10000.0, -(double)j / 16.0);
        double ang = (double)s * (double)invf;
        g_sin[id] = (float)sin(ang);
        g_cos[id] = (float)cos(ang);
    } else if (blk < 832) {                      // w_qkv: 128*1536 = 196608
        int id = (blk - 64) * 256 + tid;
        int kp = id / O1_, o = id - kp * O1_;
        uint32_t hp, lp;
        split_pack_bf16(w_qkv[(size_t)o * 256 + 2 * kp],
                        w_qkv[(size_t)o * 256 + 2 * kp + 1], hp, lp);
        g_wqh[id] = hp; g_wql[id] = lp;
    } else if (blk < 1088) {                     // w_out: 256*256 = 65536
        int id = (blk - 832) * 256 + tid;
        int kp = id / C_, o = id - kp * C_;
        uint32_t hp, lp;
        split_pack_bf16(w_out[(size_t)o * 512 + 2 * kp],
                        w_out[(size_t)o * 512 + 2 * kp + 1], hp, lp);
        g_woh[id] = hp; g_wol[id] = lp;
    } else {                                     // x split: 8*128*256 thread-groups
        int id = (blk - 1088) * 256 + tid;
        int s4 = (id & 255) * 4;
        int kp = (id >> 8) & 127;
        int b  = id >> 15;
        float4 v0 = *(const float4*)(x + ((size_t)b * 256 + 2 * kp) * S_ + s4);
        float4 v1 = *(const float4*)(x + ((size_t)b * 256 + 2 * kp + 1) * S_ + s4);
        uint32_t h0, l0, h1, l1, h2, l2, h3, l3;
        split_pack_bf16(v0.x, v1.x, h0, l0);
        split_pack_bf16(v0.y, v1.y, h1, l1);
        split_pack_bf16(v0.z, v1.z, h2, l2);
        split_pack_bf16(v0.w, v1.w, h3, l3);
        size_t oidx = ((size_t)b * 128 + kp) * S_ + s4;
        *(uint4*)(g_xh + oidx) = make_uint4(h0, h1, h2, h3);
        *(uint4*)(g_xl + oidx) = make_uint4(l0, l1, l2, l3);
    }
}

// ---------------------------------------------------------------------------
// 1+4) bf16 3-term GEMM on PRE-SPLIT operands, cp.async double-buffered.
// ---------------------------------------------------------------------------
#define GA_H0 0
#define GA_H1 576
#define GA_L0 1152
#define GA_L1 1728
#define GB_H0 2304
#define GB_H1 3392
#define GB_L0 4480
#define GB_L1 5568
#define G_SMEM_WORDS 6656

template<int KDIM, bool BIAS, bool ROPE>
__global__ __launch_bounds__(256) void gemm_pre_kernel(
    const uint32_t* __restrict__ Wh, const uint32_t* __restrict__ Wl,
    const uint32_t* __restrict__ Xh, const uint32_t* __restrict__ Xl,
    const float* __restrict__ bias, float* __restrict__ C, int Mtot)
{
    constexpr int KP = KDIM / 2;
    constexpr int NC = KDIM / 16;

    __shared__ uint32_t smg[G_SMEM_WORDS];

    const int tid  = threadIdx.x;
    const int lane = tid & 31, warp = tid >> 5;
    const int g = lane >> 2, tg = lane & 3;
    const int wm = warp & 1, wn = warp >> 1;
    const int mbase = wm * 32, nbase = wn * 32;

    const int s0 = blockIdx.x * 128;
    const int o0 = blockIdx.y * 64;
    const int b  = blockIdx.z;

    uint32_t smbase = (uint32_t)__cvta_generic_to_shared(smg);

    const int ar = (tid & 127) >> 4;
    const int aq = tid & 15;
    const bool alo = tid >= 128;
    const int br = tid >> 5;
    const int bq = tid & 31;

    const uint32_t* Wsrc = alo ? Wl : Wh;
    const uint32_t* XhB = Xh + (size_t)b * KP * S_ + s0;
    const uint32_t* XlB = Xl + (size_t)b * KP * S_ + s0;

    auto issue = [&](int chunk, int buf) {
        int kp0 = chunk * 8;
        uint32_t aoff = alo ? (buf ? GA_L1 : GA_L0) : (buf ? GA_H1 : GA_H0);
        cp_async16(smbase + (aoff + ar * 72 + aq * 4) * 4,
                   Wsrc + (size_t)(kp0 + ar) * Mtot + o0 + aq * 4);
        uint32_t bhoff = buf ? GB_H1 : GB_H0;
        uint32_t bloff = buf ? GB_L1 : GB_L0;
        cp_async16(smbase + (bhoff + br * 136 + bq * 4) * 4,
                   XhB + (size_t)(kp0 + br) * S_ + bq * 4);
        cp_async16(smbase + (bloff + br * 136 + bq * 4) * 4,
                   XlB + (size_t)(kp0 + br) * S_ + bq * 4);
    };

    issue(0, 0);
    CP_COMMIT();

    float acc[2][4][4] = {};

    for (int c = 0; c < NC; c++) {
        const int cur = c & 1;
        if (c + 1 < NC) {
            issue(c + 1, cur ^ 1);
            CP_COMMIT();
            CP_WAIT1();
        } else {
            CP_WAIT0();
        }
        __syncthreads();

        const uint32_t* AhP = smg + (cur ? GA_H1 : GA_H0);
        const uint32_t* AlP = smg + (cur ? GA_L1 : GA_L0);
        const uint32_t* BhP = smg + (cur ? GB_H1 : GB_H0);
        const uint32_t* BlP = smg + (cur ? GB_L1 : GB_L0);

        uint32_t ah[2][4], al[2][4];
#pragma unroll
        for (int mt = 0; mt < 2; mt++) {
            int r = mbase + mt * 16 + g;
            ah[mt][0] = AhP[tg * 72 + r];
            ah[mt][1] = AhP[tg * 72 + r + 8];
            ah[mt][2] = AhP[(tg + 4) * 72 + r];
            ah[mt][3] = AhP[(tg + 4) * 72 + r + 8];
            al[mt][0] = AlP[tg * 72 + r];
            al[mt][1] = AlP[tg * 72 + r + 8];
            al[mt][2] = AlP[(tg + 4) * 72 + r];
            al[mt][3] = AlP[(tg + 4) * 72 + r + 8];
        }
        uint32_t bh[4][2], bl[4][2];
#pragma unroll
        for (int nt = 0; nt < 4; nt++) {
            int n = nbase + nt * 8 + g;
            bh[nt][0] = BhP[tg * 136 + n];
            bh[nt][1] = BhP[(tg + 4) * 136 + n];
            bl[nt][0] = BlP[tg * 136 + n];
            bl[nt][1] = BlP[(tg + 4) * 136 + n];
        }
#pragma unroll
        for (int mt = 0; mt < 2; mt++)
#pragma unroll
            for (int nt = 0; nt < 4; nt++) {
                mma_bf16(acc[mt][nt], ah[mt][0], ah[mt][1], ah[mt][2], ah[mt][3], bh[nt][0], bh[nt][1]);
                mma_bf16(acc[mt][nt], ah[mt][0], ah[mt][1], ah[mt][2], ah[mt][3], bl[nt][0], bl[nt][1]);
                mma_bf16(acc[mt][nt], al[mt][0], al[mt][1], al[mt][2], al[mt][3], bh[nt][0], bh[nt][1]);
            }
        __syncthreads();
    }

    if (ROPE && o0 < 2 * HID_ && wm == 0) {
#pragma unroll
        for (int rh = 0; rh < 2; rh++) {
            int d = rh * 8 + g;
#pragma unroll
            for (int nt = 0; nt < 4; nt++)
#pragma unroll
                for (int cl = 0; cl < 2; cl++) {
                    int col = s0 + nbase + nt * 8 + tg * 2 + cl;
                    float cs = g_cos[col * 16 + d];
                    float sn = g_sin[col * 16 + d];
                    float x = acc[0][nt][rh * 2 + cl];
                    float y = acc[1][nt][rh * 2 + cl];
                    acc[0][nt][rh * 2 + cl] = x * cs - y * sn;
                    acc[1][nt][rh * 2 + cl] = y * cs + x * sn;
                }
        }
    }

    float* Cp = C + ((size_t)b * Mtot + o0) * S_ + s0;
#pragma unroll
    for (int mt = 0; mt < 2; mt++)
#pragma unroll
        for (int rh = 0; rh < 2; rh++) {
            int row = mbase + mt * 16 + rh * 8 + g;
            float bv = BIAS ? bias[o0 + row] : 0.f;
#pragma unroll
            for (int nt = 0; nt < 4; nt++) {
                int col = nbase + nt * 8 + tg * 2;
                float2 v2 = make_float2(acc[mt][nt][rh * 2 + 0] + bv,
                                        acc[mt][nt][rh * 2 + 1] + bv);
                *(float2*)(Cp + (size_t)row * S_ + col) = v2;
            }
        }
}

// ---------------------------------------------------------------------------
// 2b) L2 norm over the sequence axis (in-place on fp32 qkv)
// ---------------------------------------------------------------------------
__global__ __launch_bounds__(256) void l2norm_kernel(float* __restrict__ qkv)
{
    int row = blockIdx.x;
    int b = row >> 10;
    int o = row & 1023;
    float* p = qkv + ((size_t)b * O1_ + o) * S_;

    int tid = threadIdx.x;
    float4 v = *(float4*)(p + tid * 4);
    float ss = v.x * v.x + v.y * v.y + v.z * v.z + v.w * v.w;
#pragma unroll
    for (int off = 16; off; off >>= 1)
        ss += __shfl_xor_sync(0xffffffffu, ss, off);

    __shared__ float wss[8];
    if ((tid & 31) == 0) wss[tid >> 5] = ss;
    __syncthreads();
    if (tid < 32) {
        float t = (tid < 8) ? wss[tid] : 0.f;
#pragma unroll
        for (int off = 4; off; off >>= 1)
            t += __shfl_xor_sync(0xffffffffu, t, off);
        if (tid == 0) wss[0] = t;
    }
    __syncthreads();

    float inv = 1.0f / fmaxf(sqrtf(wss[0]), 1e-12f);
    v.x *= inv; v.y *= inv; v.z *= inv; v.w *= inv;
    *(float4*)(p + tid * 4) = v;
}

// ---------------------------------------------------------------------------
// 3) Attention (R12 config + fragment-major Q buffer):
//    Q fragments replicated once into Qf[wi][kk][mt][lane][4] (16 KB) so the
//    per-iteration A-fragment load is ONE float4 LDS (16 issue slots/iter
//    instead of 64).  2 blocks/SM, double-buffered cp.async K/V (j-tile 64),
//    register-resident P, staged O reduction, bf16 hi/lo packed output.
// ---------------------------------------------------------------------------
#define AT_QS 0            // 64*72 = 4608 (reused as Ot stride 68 in epilogue)
#define AT_K0 4608
#define AT_K1 9216
#define AT_V0 13824        // 64*68 = 4352
#define AT_V1 18176
#define AT_L  22528        // 64
#define AT_QF 22592        // 2*8*2*128 = 4096 fragment-major Q
#define AT_SMEM_FLOATS 26688   // 106.8 KB

__global__ __launch_bounds__(256, 2) void attn_tc_kernel(
    const float* __restrict__ qkv,
    uint32_t* __restrict__ Oh, uint32_t* __restrict__ Ol)
{
    extern __shared__ float sm[];
    float* Qs  = sm + AT_QS;
    float* Lsm = sm + AT_L;
    float* Qf  = sm + AT_QF;

    const int tid  = threadIdx.x;
    const int lane = tid & 31;
    const int warp = tid >> 5;
    const int g  = lane >> 2;
    const int tg = lane & 3;
    const int wi = warp & 1;
    const int wq = warp >> 1;          // 0..3: 16-j slice
    const int ib = wi * 32;
    const int jh = wq * 16;
    const int fg = (g >> 1) | ((g & 1) << 2);   // K column permutation

    const int i0 = blockIdx.x * 64;
    const int h  = blockIdx.y;
    const int b  = blockIdx.z;

    const float* Qg = qkv + ((size_t)b * O1_ + h * D_) * S_;
    const float* Kg = Qg + (size_t)HID_ * S_;
    const float* Vg = Qg + (size_t)(2 * HID_) * S_;

    uint32_t smbase = (uint32_t)__cvta_generic_to_shared(sm);

    // Q tile [d][i], stride 72
    for (int v = tid; v < 1024; v += 256) {
        int d = v >> 4, iq = v & 15;
        *(float4*)&Qs[d * 72 + iq * 4] =
            *(const float4*)(Qg + (size_t)d * S_ + i0 + iq * 4);
    }
    if (tid < 64) Lsm[tid] = 0.f;

    const int ldd = tid >> 4, ljq = tid & 15;
    auto issue_kv = [&](int buf, int j0) {
        uint32_t koff = (buf ? AT_K1 : AT_K0);
        uint32_t voff = (buf ? AT_V1 : AT_V0);
#pragma unroll
        for (int r = 0; r < 4; r++) {
            int d = ldd + r * 16;
            cp_async16(smbase + (koff + d * 72 + ljq * 4) * 4,
                       Kg + (size_t)d * S_ + j0 + ljq * 4);
            cp_async16(smbase + (voff + d * 68 + ljq * 4) * 4,
                       Vg + (size_t)d * S_ + j0 + ljq * 4);
        }
    };

    issue_kv(0, 0);
    CP_COMMIT();
    __syncthreads();   // Qs complete before fragment build

    // Build fragment-major Q: warps wq==0 (one per i-half) write their frags.
    if (wq == 0) {
#pragma unroll
        for (int kk = 0; kk < 8; kk++) {
            const int k0 = kk * 8;
#pragma unroll
            for (int mt = 0; mt < 2; mt++) {
                int r = ib + mt * 16 + g;
                float4 qa;
                qa.x = Qs[(k0 + tg) * 72 + r];
                qa.y = Qs[(k0 + tg) * 72 + r + 8];
                qa.z = Qs[(k0 + tg + 4) * 72 + r];
                qa.w = Qs[(k0 + tg + 4) * 72 + r + 8];
                *(float4*)&Qf[(((wi * 8) + kk) * 2 + mt) * 128 + lane * 4] = qa;
            }
        }
    }
    __syncthreads();

    float oacc[2][8][4] = {};
    float l_acc[2][2]   = {};

    for (int it = 0; it < 16; it++) {
        const int cur = it & 1;
        __syncthreads();
        if (it + 1 < 16) {
            issue_kv(cur ^ 1, (it + 1) * 64);
            CP_COMMIT();
            CP_WAIT1();
        } else {
            CP_WAIT0();
        }
        __syncthreads();

        const float* Ks = sm + (cur ? AT_K1 : AT_K0);
        const float* Vs = sm + (cur ? AT_V1 : AT_V0);

        // ---- S phase: S[32 i][16 j]; A-fragments via one float4 LDS each
        float sacc[2][2][4] = {};
#pragma unroll
        for (int kk = 0; kk < 8; kk++) {
            const int k0 = kk * 8;
            uint4 a[2];
#pragma unroll
            for (int mt = 0; mt < 2; mt++)
                a[mt] = *(uint4*)&Qf[(((wi * 8) + kk) * 2 + mt) * 128 + lane * 4];
            uint32_t bb[2][2];
#pragma unroll
            for (int nt = 0; nt < 2; nt++) {
                int jc = jh + nt * 8 + fg;
                bb[nt][0] = __float_as_uint(Ks[(k0 + tg) * 72 + jc]);
                bb[nt][1] = __float_as_uint(Ks[(k0 + tg + 4) * 72 + jc]);
            }
#pragma unroll
            for (int mt = 0; mt < 2; mt++)
#pragma unroll
                for (int nt = 0; nt < 2; nt++)
                    mma_tf32(sacc[mt][nt], a[mt].x, a[mt].y, a[mt].z, a[mt].w,
                             bb[nt][0], bb[nt][1]);
        }

        // ---- exp in place + row sums
#pragma unroll
        for (int mt = 0; mt < 2; mt++)
#pragma unroll
            for (int nt = 0; nt < 2; nt++) {
                float p0 = __expf(10.f * sacc[mt][nt][0]);
                float p1 = __expf(10.f * sacc[mt][nt][1]);
                float p2 = __expf(10.f * sacc[mt][nt][2]);
                float p3 = __expf(10.f * sacc[mt][nt][3]);
                sacc[mt][nt][0] = p0; sacc[mt][nt][1] = p1;
                sacc[mt][nt][2] = p2; sacc[mt][nt][3] = p3;
                l_acc[mt][0] += p0 + p1;
                l_acc[mt][1] += p2 + p3;
            }

        // ---- O phase: P (registers) x V^T, n = all 64 d, k = 16 j
#pragma unroll
        for (int ks = 0; ks < 2; ks++) {
            const int jk = jh + ks * 8;
            uint32_t bb[8][2];
#pragma unroll
            for (int nt = 0; nt < 8; nt++) {
                int dc = nt * 8 + g;
                bb[nt][0] = __float_as_uint(Vs[dc * 68 + jk + tg]);
                bb[nt][1] = __float_as_uint(Vs[dc * 68 + jk + tg + 4]);
            }
#pragma unroll
            for (int mt = 0; mt < 2; mt++) {
                uint32_t a0 = __float_as_uint(sacc[mt][ks][0]);
                uint32_t a1 = __float_as_uint(sacc[mt][ks][2]);
                uint32_t a2 = __float_as_uint(sacc[mt][ks][1]);
                uint32_t a3 = __float_as_uint(sacc[mt][ks][3]);
#pragma unroll
                for (int nt = 0; nt < 8; nt++)
                    mma_tf32(oacc[mt][nt], a0, a1, a2, a3, bb[nt][0], bb[nt][1]);
            }
        }
    }

    // ---- row sums: reduce over tg lanes, merge 4 j-warps via atomicAdd
#pragma unroll
    for (int mt = 0; mt < 2; mt++)
#pragma unroll
        for (int rh = 0; rh < 2; rh++) {
            float l = l_acc[mt][rh];
            l += __shfl_xor_sync(0xffffffffu, l, 1);
            l += __shfl_xor_sync(0xffffffffu, l, 2);
            if (tg == 0)
                atomicAdd(&Lsm[ib + mt * 16 + rh * 8 + g], l);
        }
    __syncthreads();

    // ---- staged reduction of partial O across 4 j-warps into Ot=Qs (str 68)
#pragma unroll
    for (int r = 0; r < 4; r++) {
        if (wq == r) {
#pragma unroll
            for (int mt = 0; mt < 2; mt++)
#pragma unroll
                for (int nt = 0; nt < 8; nt++)
#pragma unroll
                    for (int c = 0; c < 4; c++) {
                        int row = ib + mt * 16 + g + ((c >> 1) << 3);
                        int col = nt * 8 + tg * 2 + (c & 1);
                        if (r == 0) Qs[col * 68 + row] = oacc[mt][nt][c];
                        else        Qs[col * 68 + row] += oacc[mt][nt][c];
                    }
        }
        __syncthreads();
    }

    if (tid < 64) Lsm[tid] = 1.0f / Lsm[tid];
    __syncthreads();

    // ---- normalized store as packed bf16 hi/lo d-pairs: O[b][kp][s]
    for (int v = tid; v < 512; v += 256) {
        int p = v >> 4, iq = v & 15;
        float4 o0 = *(float4*)&Qs[(2 * p) * 68 + iq * 4];
        float4 o1 = *(float4*)&Qs[(2 * p + 1) * 68 + iq * 4];
        float i0s = Lsm[iq * 4 + 0], i1s = Lsm[iq * 4 + 1];
        float i2s = Lsm[iq * 4 + 2], i3s = Lsm[iq * 4 + 3];
        o0.x *= i0s; o0.y *= i1s; o0.z *= i2s; o0.w *= i3s;
        o1.x *= i0s; o1.y *= i1s; o1.z *= i2s; o1.w *= i3s;
        uint32_t h0, l0, h1, l1, h2, l2, h3, l3;
        split_pack_bf16(o0.x, o1.x, h0, l0);
        split_pack_bf16(o0.y, o1.y, h1, l1);
        split_pack_bf16(o0.z, o1.z, h2, l2);
        split_pack_bf16(o0.w, o1.w, h3, l3);
        size_t oidx = ((size_t)b * 256 + h * 32 + p) * S_ + i0 + iq * 4;
        *(uint4*)(Oh + oidx) = make_uint4(h0, h1, h2, h3);
        *(uint4*)(Ol + oidx) = make_uint4(l0, l1, l2, l3);
    }
}

// ---------------------------------------------------------------------------
// Launch
// ---------------------------------------------------------------------------
extern "C" void kernel_launch(void* const* d_in, const int* in_sizes, int n_in,
                              void* d_out, int out_size)
{
    const float* x     = (const float*)d_in[0];
    const float* w_qkv = (const float*)d_in[1];
    const float* w_out = (const float*)d_in[2];
    const float* b_out = (const float*)d_in[3];
    float* out = (float*)d_out;

    float* qkv;   cudaGetSymbolAddress((void**)&qkv, g_qkv);
    uint32_t *wqh, *wql, *woh, *wol, *xh, *xl, *oh, *ol;
    cudaGetSymbolAddress((void**)&wqh, g_wqh);
    cudaGetSymbolAddress((void**)&wql, g_wql);
    cudaGetSymbolAddress((void**)&woh, g_woh);
    cudaGetSymbolAddress((void**)&wol, g_wol);
    cudaGetSymbolAddress((void**)&xh, g_xh);
    cudaGetSymbolAddress((void**)&xl, g_xl);
    cudaGetSymbolAddress((void**)&oh, g_oh);
    cudaGetSymbolAddress((void**)&ol, g_ol);

    static const size_t attn_smem = AT_SMEM_FLOATS * sizeof(float);  // ~107 KB
    cudaFuncSetAttribute(attn_tc_kernel,
                         cudaFuncAttributeMaxDynamicSharedMemorySize,
                         (int)attn_smem);

    // fused prep: sin/cos + weight splits + x split (one launch)
    prep_kernel<<<2112, 256>>>(x, w_qkv, w_out);

    {   // QKV projection (pre-split bf16x3, fused RoPE on q/k tiles)
        dim3 grid(S_ / 128, O1_ / 64, B_);
        gemm_pre_kernel<256, false, true><<<grid, 256>>>(wqh, wql, xh, xl,
                                                         nullptr, qkv, O1_);
    }

    l2norm_kernel<<<B_ * 2 * HID_, 256>>>(qkv);

    {   // Attention (fragment-major Q, 2 blocks/SM, double-buffered K/V)
        dim3 grid(S_ / 64, H_, B_);
        attn_tc_kernel<<<grid, 256, attn_smem>>>(qkv, oh, ol);
    }

    {   // Output projection (pre-split bf16x3 + bias)
        dim3 grid(S_ / 128, C_ / 64, B_);
        gemm_pre_kernel<512, true, false><<<grid, 256>>>(woh, wol, oh, ol,
                                                         b_out, out, C_);
    }
}